// round 8
// baseline (speedup 1.0000x reference)
#include <cuda_runtime.h>
#include <math.h>
#include <stdint.h>

// Problem constants
#define L_TOK   65536      // H*W tokens
#define IMGW    256
#define DIMC    180
#define NHEADS  6
#define HD      30
#define HDP     32         // padded head dim (128B rows, float4)
#define NWIN    256        // 16x16 windows
#define NQ      256        // WS*WS
#define NKV     576        // OWS*OWS
#define NKVH    288        // half window (two-stage smem)
#define MLPH    360
#define QKVW    540        // 3*DIMC

typedef unsigned long long ull;

// ---------------- packed f32x2 helpers (Blackwell FFMA2 path) ----------
__device__ __forceinline__ ull pack2(float x, float y) {
    ull r; asm("mov.b64 %0, {%1, %2};" : "=l"(r) : "f"(x), "f"(y)); return r;
}
__device__ __forceinline__ ull dup2(float x) { return pack2(x, x); }
__device__ __forceinline__ void unpack2(ull v, float& x, float& y) {
    asm("mov.b64 {%0, %1}, %2;" : "=f"(x), "=f"(y) : "l"(v));
}
__device__ __forceinline__ void ffma2(ull& d, ull a, ull b) {
    asm("fma.rn.f32x2 %0, %1, %2, %0;" : "+l"(d) : "l"(a), "l"(b));
}
__device__ __forceinline__ void fmul2(ull& d, ull a) {
    asm("mul.rn.f32x2 %0, %1, %2;" : "=l"(d) : "l"(d), "l"(a));
}

// -------- scratch (static device arrays; no allocation allowed) --------
__device__ float g_xn  [(size_t)L_TOK * DIMC];
__device__ float g_qkv [(size_t)L_TOK * QKVW];
__device__ float g_biasT[(size_t)NHEADS * NKV * NQ];   // [h][k][q]
__device__ float g_attn[(size_t)L_TOK * DIMC];
__device__ float g_xo  [(size_t)L_TOK * DIMC];
__device__ float g_xn2 [(size_t)L_TOK * DIMC];
__device__ float g_hid [(size_t)L_TOK * MLPH];

// ----------------------------- LayerNorm -----------------------------
__global__ void ln_kernel(const float* __restrict__ x,
                          const float* __restrict__ g,
                          const float* __restrict__ b,
                          float* __restrict__ y) {
    int token = blockIdx.x * blockDim.y + threadIdx.y;
    int lane  = threadIdx.x;
    const float* xr = x + (size_t)token * DIMC;

    float v[6];
    float s = 0.f;
#pragma unroll
    for (int j = 0; j < 6; j++) {
        int ch = lane + 32 * j;
        v[j] = (ch < DIMC) ? xr[ch] : 0.f;
        s += v[j];
    }
#pragma unroll
    for (int o = 16; o > 0; o >>= 1) s += __shfl_xor_sync(0xffffffff, s, o);
    float mean = s * (1.0f / DIMC);

    float s2 = 0.f;
#pragma unroll
    for (int j = 0; j < 6; j++) {
        int ch = lane + 32 * j;
        float d = (ch < DIMC) ? (v[j] - mean) : 0.f;
        s2 += d * d;
    }
#pragma unroll
    for (int o = 16; o > 0; o >>= 1) s2 += __shfl_xor_sync(0xffffffff, s2, o);
    float rstd = rsqrtf(s2 * (1.0f / DIMC) + 1e-5f);

    float* yr = y + (size_t)token * DIMC;
#pragma unroll
    for (int j = 0; j < 6; j++) {
        int ch = lane + 32 * j;
        if (ch < DIMC) yr[ch] = g[ch] * (v[j] - mean) * rstd + b[ch];
    }
}

// ------------------------- bias precompute --------------------------
__global__ void bias_kernel(const int* __restrict__ rpi,
                            const float* __restrict__ table,
                            float* __restrict__ biasT) {
    int q = threadIdx.x;      // 0..255
    int k = blockIdx.x;       // 0..575
    int h = blockIdx.y;       // 0..5
    biasT[((size_t)h * NKV + k) * NQ + q] = table[rpi[q * NKV + k] * NHEADS + h];
}

// ------------------------------ SGEMM -------------------------------
// C[m*ldc+n] = A[M,K] @ B[K,N] + bias[n]  (+ epilogue)
// EPI: 0 = bias, 1 = bias + exact GELU, 2 = bias + residual res[m*N+n]
// BM=128, BN=64, BK=20. Packed fma.rn.f32x2 microkernel, register-staged
// smem double buffering, fully vectorized (float4) epilogue.
#define BM 128
#define BN 64
#define BK 20

template <int EPI>
__global__ void __launch_bounds__(256) sgemm(
    const float* __restrict__ A, const float* __restrict__ B,
    const float* __restrict__ bias, const float* __restrict__ res,
    float* __restrict__ C, int M, int N, int K, int ldc) {

    __shared__ __align__(16) float As[2][BK][BM];
    __shared__ __align__(16) float Bs[2][BK][BN];

    int tid = threadIdx.x;
    int tx = tid & 15;         // 16 columns of threads (N)
    int ty = tid >> 4;         // 16 rows of threads (M)
    int m0 = blockIdx.x * BM;
    int n0 = blockIdx.y * BN;

    int a_row[3], a_kq[3];
#pragma unroll
    for (int j = 0; j < 3; j++) {
        int idx = tid + 256 * j;
        a_row[j] = idx / 5;
        a_kq[j]  = idx % 5;
    }
    const bool a_v2 = (tid < 128);
    int b_kk[2], b_nq[2];
#pragma unroll
    for (int j = 0; j < 2; j++) {
        int idx = tid + 256 * j;
        b_kk[j] = idx / 16;
        b_nq[j] = idx % 16;
    }
    const bool b_v1 = (tid < 64);

    float4 ra[3], rb[2];

#define LOAD_STAGE(k0)                                                        \
    {                                                                          \
        ra[0] = *reinterpret_cast<const float4*>(                              \
            &A[(size_t)(m0 + a_row[0]) * K + (k0) + a_kq[0] * 4]);             \
        ra[1] = *reinterpret_cast<const float4*>(                              \
            &A[(size_t)(m0 + a_row[1]) * K + (k0) + a_kq[1] * 4]);             \
        if (a_v2) ra[2] = *reinterpret_cast<const float4*>(                    \
            &A[(size_t)(m0 + a_row[2]) * K + (k0) + a_kq[2] * 4]);             \
        {                                                                      \
            int n = n0 + b_nq[0] * 4;                                          \
            rb[0] = (n < N) ? *reinterpret_cast<const float4*>(                \
                        &B[(size_t)((k0) + b_kk[0]) * N + n])                  \
                            : make_float4(0.f, 0.f, 0.f, 0.f);                 \
        }                                                                      \
        if (b_v1) {                                                            \
            int n = n0 + b_nq[1] * 4;                                          \
            rb[1] = (n < N) ? *reinterpret_cast<const float4*>(                \
                        &B[(size_t)((k0) + b_kk[1]) * N + n])                  \
                            : make_float4(0.f, 0.f, 0.f, 0.f);                 \
        }                                                                      \
    }

#define STORE_STAGE(buf)                                                      \
    {                                                                          \
        As[buf][a_kq[0] * 4 + 0][a_row[0]] = ra[0].x;                          \
        As[buf][a_kq[0] * 4 + 1][a_row[0]] = ra[0].y;                          \
        As[buf][a_kq[0] * 4 + 2][a_row[0]] = ra[0].z;                          \
        As[buf][a_kq[0] * 4 + 3][a_row[0]] = ra[0].w;                          \
        As[buf][a_kq[1] * 4 + 0][a_row[1]] = ra[1].x;                          \
        As[buf][a_kq[1] * 4 + 1][a_row[1]] = ra[1].y;                          \
        As[buf][a_kq[1] * 4 + 2][a_row[1]] = ra[1].z;                          \
        As[buf][a_kq[1] * 4 + 3][a_row[1]] = ra[1].w;                          \
        if (a_v2) {                                                            \
            As[buf][a_kq[2] * 4 + 0][a_row[2]] = ra[2].x;                      \
            As[buf][a_kq[2] * 4 + 1][a_row[2]] = ra[2].y;                      \
            As[buf][a_kq[2] * 4 + 2][a_row[2]] = ra[2].z;                      \
            As[buf][a_kq[2] * 4 + 3][a_row[2]] = ra[2].w;                      \
        }                                                                      \
        *reinterpret_cast<float4*>(&Bs[buf][b_kk[0]][b_nq[0] * 4]) = rb[0];    \
        if (b_v1)                                                              \
            *reinterpret_cast<float4*>(&Bs[buf][b_kk[1]][b_nq[1] * 4]) = rb[1];\
    }

    ull acc2[4][4];
#pragma unroll
    for (int i = 0; i < 4; i++)
#pragma unroll
        for (int j = 0; j < 4; j++) acc2[i][j] = 0ull;

    int nstage = K / BK;

    LOAD_STAGE(0)
    STORE_STAGE(0)
    __syncthreads();

    for (int kt = 0; kt < nstage; kt++) {
        int buf = kt & 1;
        if (kt + 1 < nstage) LOAD_STAGE((kt + 1) * BK)   // LDG overlaps compute

#pragma unroll
        for (int kk = 0; kk < BK; kk++) {
            ulonglong2 a01 = *reinterpret_cast<const ulonglong2*>(&As[buf][kk][ty * 8]);
            ulonglong2 a23 = *reinterpret_cast<const ulonglong2*>(&As[buf][kk][ty * 8 + 4]);
            float4 b0 = *reinterpret_cast<const float4*>(&Bs[buf][kk][tx * 4]);
            ull ap[4] = {a01.x, a01.y, a23.x, a23.y};
            ull bd[4] = {dup2(b0.x), dup2(b0.y), dup2(b0.z), dup2(b0.w)};
#pragma unroll
            for (int i = 0; i < 4; i++)
#pragma unroll
                for (int j = 0; j < 4; j++) ffma2(acc2[i][j], ap[i], bd[j]);
        }

        if (kt + 1 < nstage) STORE_STAGE(buf ^ 1)
        __syncthreads();
    }

    // -------- vectorized epilogue: quads are wholly in- or out-of-range
    // (N % 4 == 0), all row strides 16B-aligned --------
    int n4 = n0 + tx * 4;
    if (n4 < N) {
        float4 bv = *reinterpret_cast<const float4*>(&bias[n4]);
        float bb[4] = {bv.x, bv.y, bv.z, bv.w};
#pragma unroll
        for (int i2 = 0; i2 < 4; i2++) {
            float va[2][4];
#pragma unroll
            for (int j = 0; j < 4; j++) unpack2(acc2[i2][j], va[0][j], va[1][j]);
#pragma unroll
            for (int r = 0; r < 2; r++) {
                int ma = m0 + ty * 8 + 2 * i2 + r;
#pragma unroll
                for (int j = 0; j < 4; j++) {
                    float v = va[r][j] + bb[j];
                    if (EPI == 1)
                        v = 0.5f * v * (1.0f + erff(v * 0.70710678118654752f));
                    va[r][j] = v;
                }
                if (EPI == 2) {
                    float4 rv = *reinterpret_cast<const float4*>(
                        &res[(size_t)ma * N + n4]);
                    va[r][0] += rv.x; va[r][1] += rv.y;
                    va[r][2] += rv.z; va[r][3] += rv.w;
                }
                *reinterpret_cast<float4*>(&C[(size_t)ma * ldc + n4]) =
                    make_float4(va[r][0], va[r][1], va[r][2], va[r][3]);
            }
        }
    }
#undef LOAD_STAGE
#undef STORE_STAGE
}

// ---------------------------- Attention -----------------------------
// One block per (window, head): 256 threads, one query each.
// KV processed in TWO halves of 288 keys so smem = 73.7KB -> 2 CTAs/SM:
// one CTA's staging overlaps the co-resident CTA's compute, and 4 warps/SMSP
// cover exp/bias bubbles. Online softmax state carries across halves.
// Staging loop unrolled (compile-time 18 iters) to batch LDG.64s.
// Packed f32x2 inner loop, bias prefetched 2 iterations ahead.
__global__ void __launch_bounds__(256, 2) attn_kernel(
    const float* __restrict__ qkv, const float* __restrict__ biasT,
    float* __restrict__ out) {

    extern __shared__ float smem[];
    float* ksm = smem;                     // NKVH * HDP floats
    float* vsm = smem + NKVH * HDP;        // NKVH * HDP floats

    int win = blockIdx.x;
    int h   = blockIdx.y;
    int wy  = win >> 4, wx = win & 15;
    int tid = threadIdx.x;

    int qy = tid >> 4, qx = tid & 15;
    size_t pix = (size_t)(wy * 16 + qy) * IMGW + (wx * 16 + qx);
    const float scale = rsqrtf((float)HD);
    ull q2[16];
    {
        float qtmp[HDP];
        const float* qp = qkv + pix * QKVW + h * HD;
#pragma unroll
        for (int d = 0; d < HD; d++) qtmp[d] = qp[d] * scale;
        qtmp[30] = 0.f; qtmp[31] = 0.f;
#pragma unroll
        for (int i = 0; i < 16; i++) q2[i] = pack2(qtmp[2 * i], qtmp[2 * i + 1]);
    }

    const float* bT = biasT + (size_t)h * NKV * NQ + tid;
    float m = -1e30f, l = 0.f;
    ull acc2[16];
#pragma unroll
    for (int i = 0; i < 16; i++) acc2[i] = 0ull;

    // 2-deep rolling bias prefetch (global key index)
    float bcur = bT[0];
    float bnx1 = bT[NQ];

    for (int half = 0; half < 2; half++) {
        int kbase = half * NKVH;
        __syncthreads();   // previous half's compute done before restage

        // stage 288 keys as float2: 16 slots per key (slot 15 = pad 30,31)
#pragma unroll 6
        for (int idx = tid; idx < NKVH * 16; idx += 256) {
            int loc = idx >> 4;            // local key 0..287
            int dd  = idx & 15;            // float2 slot
            int pos = kbase + loc;
            int ky = pos / 24, kx = pos - ky * 24;
            int r = wy * 16 - 4 + ky;
            int c = wx * 16 - 4 + kx;
            float2 kk = make_float2(0.f, 0.f), vv = make_float2(0.f, 0.f);
            if (dd < 15 && (unsigned)r < (unsigned)IMGW && (unsigned)c < (unsigned)IMGW) {
                const float* base = qkv + (size_t)(r * IMGW + c) * QKVW + h * HD + 2 * dd;
                kk = *reinterpret_cast<const float2*>(base + DIMC);       // K
                vv = *reinterpret_cast<const float2*>(base + 2 * DIMC);   // V
            }
            *reinterpret_cast<float2*>(ksm + loc * HDP + 2 * dd) = kk;
            *reinterpret_cast<float2*>(vsm + loc * HDP + 2 * dd) = vv;
        }
        __syncthreads();

        for (int kl = 0; kl < NKVH; kl++) {
            int k = kbase + kl;
            float bnx2 = (k + 2 < NKV) ? bT[(size_t)(k + 2) * NQ] : 0.f;

            const ulonglong2* kr = reinterpret_cast<const ulonglong2*>(ksm + kl * HDP);
            ull s01 = 0ull, s23 = 0ull, s45 = 0ull, s67 = 0ull;
#pragma unroll
            for (int i = 0; i < 4; i++) {
                ulonglong2 ka = kr[2 * i];
                ulonglong2 kb = kr[2 * i + 1];
                ffma2(s01, q2[4 * i + 0], ka.x);
                ffma2(s23, q2[4 * i + 1], ka.y);
                ffma2(s45, q2[4 * i + 2], kb.x);
                ffma2(s67, q2[4 * i + 3], kb.y);
            }
            float f0, f1, f2, f3, f4, f5, f6, f7;
            unpack2(s01, f0, f1); unpack2(s23, f2, f3);
            unpack2(s45, f4, f5); unpack2(s67, f6, f7);
            float s = ((f0 + f1) + (f2 + f3)) + ((f4 + f5) + (f6 + f7)) + bcur;
            bcur = bnx1; bnx1 = bnx2;

            if (s > m) {
                float cf = __expf(m - s);
                l *= cf;
                ull cf2 = dup2(cf);
#pragma unroll
                for (int i = 0; i < 16; i++) fmul2(acc2[i], cf2);
                m = s;
            }
            float e = __expf(s - m);
            l += e;
            ull e2 = dup2(e);
            const ulonglong2* vr = reinterpret_cast<const ulonglong2*>(vsm + kl * HDP);
#pragma unroll
            for (int i = 0; i < 8; i++) {
                ulonglong2 vv = vr[i];
                ffma2(acc2[2 * i], e2, vv.x);
                ffma2(acc2[2 * i + 1], e2, vv.y);
            }
        }
    }

    float inv = 1.f / l;
    float accf[HDP];
#pragma unroll
    for (int i = 0; i < 16; i++) unpack2(acc2[i], accf[2 * i], accf[2 * i + 1]);
    float* op = out + pix * DIMC + h * HD;
#pragma unroll
    for (int d = 0; d < HD; d++) op[d] = accf[d] * inv;
}

// ---------------------------- launch --------------------------------
extern "C" void kernel_launch(void* const* d_in, const int* in_sizes, int n_in,
                              void* d_out, int out_size) {
    // input order: x, rpi, [h, w,] norm1_g, norm1_b, q_w, q_b, kv_w, kv_b,
    //              rpb_table, proj_w, proj_b, norm2_g, norm2_b,
    //              mlp_w1, mlp_b1, mlp_w2, mlp_b2
    int s = (n_in >= 19) ? 2 : 0;   // skip h,w scalars if present
    const float* x    = (const float*)d_in[0];
    const int*   rpi  = (const int*)d_in[1];
    const float* n1g  = (const float*)d_in[2 + s];
    const float* n1b  = (const float*)d_in[3 + s];
    const float* qw   = (const float*)d_in[4 + s];
    const float* qb   = (const float*)d_in[5 + s];
    const float* kvw  = (const float*)d_in[6 + s];
    const float* kvb  = (const float*)d_in[7 + s];
    const float* tab  = (const float*)d_in[8 + s];
    const float* pw   = (const float*)d_in[9 + s];
    const float* pb   = (const float*)d_in[10 + s];
    const float* n2g  = (const float*)d_in[11 + s];
    const float* n2b  = (const float*)d_in[12 + s];
    const float* w1   = (const float*)d_in[13 + s];
    const float* b1   = (const float*)d_in[14 + s];
    const float* w2   = (const float*)d_in[15 + s];
    const float* b2   = (const float*)d_in[16 + s];
    float* outp = (float*)d_out;

    float *xn, *qkv, *biasT, *attn, *xo, *xn2, *hid;
    cudaGetSymbolAddress((void**)&xn,    g_xn);
    cudaGetSymbolAddress((void**)&qkv,   g_qkv);
    cudaGetSymbolAddress((void**)&biasT, g_biasT);
    cudaGetSymbolAddress((void**)&attn,  g_attn);
    cudaGetSymbolAddress((void**)&xo,    g_xo);
    cudaGetSymbolAddress((void**)&xn2,   g_xn2);
    cudaGetSymbolAddress((void**)&hid,   g_hid);

    dim3 lnb(32, 8);

    // 1) LN1
    ln_kernel<<<L_TOK / 8, lnb>>>(x, n1g, n1b, xn);
    // 2) bias table (independent of LN)
    bias_kernel<<<dim3(NKV, NHEADS), NQ>>>(rpi, tab, biasT);
    // 3) Q and KV projections into one 540-wide buffer
    sgemm<0><<<dim3(L_TOK / BM, (DIMC + BN - 1) / BN), 256>>>(
        xn, qw, qb, nullptr, qkv, L_TOK, DIMC, DIMC, QKVW);
    sgemm<0><<<dim3(L_TOK / BM, (2 * DIMC + BN - 1) / BN), 256>>>(
        xn, kvw, kvb, nullptr, qkv + DIMC, L_TOK, 2 * DIMC, DIMC, QKVW);
    // 4) fused windowed attention (half-window smem: 2*288*32*4 = 73728 B)
    size_t attn_smem = (size_t)NKVH * HDP * 2 * sizeof(float);
    cudaFuncSetAttribute(attn_kernel,
                         cudaFuncAttributeMaxDynamicSharedMemorySize,
                         (int)attn_smem);
    attn_kernel<<<dim3(NWIN, NHEADS), 256, attn_smem>>>(qkv, biasT, attn);
    // 5) output projection + residual(x)
    sgemm<2><<<dim3(L_TOK / BM, (DIMC + BN - 1) / BN), 256>>>(
        attn, pw, pb, x, xo, L_TOK, DIMC, DIMC, DIMC);
    // 6) LN2
    ln_kernel<<<L_TOK / 8, lnb>>>(xo, n2g, n2b, xn2);
    // 7) MLP up + GELU
    sgemm<1><<<dim3(L_TOK / BM, (MLPH + BN - 1) / BN), 256>>>(
        xn2, w1, b1, nullptr, hid, L_TOK, MLPH, DIMC, MLPH);
    // 8) MLP down + residual(xo) -> d_out
    sgemm<2><<<dim3(L_TOK / BM, (DIMC + BN - 1) / BN), 256>>>(
        hid, w2, b2, xo, outp, L_TOK, DIMC, MLPH, DIMC);
}

// round 11
// speedup vs baseline: 1.0006x; 1.0006x over previous
#include <cuda_runtime.h>
#include <math.h>
#include <stdint.h>

// Problem constants
#define L_TOK   65536      // H*W tokens
#define IMGW    256
#define DIMC    180
#define NHEADS  6
#define HD      30
#define HDP     32         // padded head dim (128B rows, float4)
#define NWIN    256        // 16x16 windows
#define NQ      256        // WS*WS
#define NKV     576        // OWS*OWS
#define NKVH    288        // half window (two-stage smem)
#define MLPH    360
#define QKVW    540        // 3*DIMC

typedef unsigned long long ull;

// ---------------- packed f32x2 helpers (Blackwell FFMA2 path) ----------
__device__ __forceinline__ ull pack2(float x, float y) {
    ull r; asm("mov.b64 %0, {%1, %2};" : "=l"(r) : "f"(x), "f"(y)); return r;
}
__device__ __forceinline__ ull dup2(float x) { return pack2(x, x); }
__device__ __forceinline__ void unpack2(ull v, float& x, float& y) {
    asm("mov.b64 {%0, %1}, %2;" : "=f"(x), "=f"(y) : "l"(v));
}
__device__ __forceinline__ void ffma2(ull& d, ull a, ull b) {
    asm("fma.rn.f32x2 %0, %1, %2, %0;" : "+l"(d) : "l"(a), "l"(b));
}
__device__ __forceinline__ void fmul2(ull& d, ull a) {
    asm("mul.rn.f32x2 %0, %1, %2;" : "=l"(d) : "l"(d), "l"(a));
}
__device__ __forceinline__ void fadd2(ull& d, ull a) {
    asm("add.rn.f32x2 %0, %0, %1;" : "+l"(d) : "l"(a));
}
// cp.async 16B (LDGSTS)
__device__ __forceinline__ void cp_async16(void* smem_dst, const void* gmem_src) {
    uint32_t s = (uint32_t)__cvta_generic_to_shared(smem_dst);
    asm volatile("cp.async.cg.shared.global [%0], [%1], 16;\n"
                 :: "r"(s), "l"(gmem_src));
}
__device__ __forceinline__ void cp_async_commit() {
    asm volatile("cp.async.commit_group;\n");
}
__device__ __forceinline__ void cp_async_wait0() {
    asm volatile("cp.async.wait_group 0;\n");
}

// -------- scratch (static device arrays; no allocation allowed) --------
__device__ float g_xn  [(size_t)L_TOK * DIMC];
__device__ float g_qkv [(size_t)L_TOK * QKVW];
__device__ float g_biasT[(size_t)NHEADS * NKV * NQ];   // [h][k][q]
__device__ float g_attn[(size_t)L_TOK * DIMC];
__device__ float g_xo  [(size_t)L_TOK * DIMC];
__device__ float g_xn2 [(size_t)L_TOK * DIMC];
__device__ float g_hid [(size_t)L_TOK * MLPH];

// ----------------------------- LayerNorm -----------------------------
__global__ void ln_kernel(const float* __restrict__ x,
                          const float* __restrict__ g,
                          const float* __restrict__ b,
                          float* __restrict__ y) {
    int token = blockIdx.x * blockDim.y + threadIdx.y;
    int lane  = threadIdx.x;
    const float* xr = x + (size_t)token * DIMC;

    float v[6];
    float s = 0.f;
#pragma unroll
    for (int j = 0; j < 6; j++) {
        int ch = lane + 32 * j;
        v[j] = (ch < DIMC) ? xr[ch] : 0.f;
        s += v[j];
    }
#pragma unroll
    for (int o = 16; o > 0; o >>= 1) s += __shfl_xor_sync(0xffffffff, s, o);
    float mean = s * (1.0f / DIMC);

    float s2 = 0.f;
#pragma unroll
    for (int j = 0; j < 6; j++) {
        int ch = lane + 32 * j;
        float d = (ch < DIMC) ? (v[j] - mean) : 0.f;
        s2 += d * d;
    }
#pragma unroll
    for (int o = 16; o > 0; o >>= 1) s2 += __shfl_xor_sync(0xffffffff, s2, o);
    float rstd = rsqrtf(s2 * (1.0f / DIMC) + 1e-5f);

    float* yr = y + (size_t)token * DIMC;
#pragma unroll
    for (int j = 0; j < 6; j++) {
        int ch = lane + 32 * j;
        if (ch < DIMC) yr[ch] = g[ch] * (v[j] - mean) * rstd + b[ch];
    }
}

// ------------------------- bias precompute --------------------------
__global__ void bias_kernel(const int* __restrict__ rpi,
                            const float* __restrict__ table,
                            float* __restrict__ biasT) {
    int q = threadIdx.x;      // 0..255
    int k = blockIdx.x;       // 0..575
    int h = blockIdx.y;       // 0..5
    biasT[((size_t)h * NKV + k) * NQ + q] = table[rpi[q * NKV + k] * NHEADS + h];
}

// ------------------------------ SGEMM -------------------------------
// C[m*ldc+n] = A[M,K] @ B[K,N] + bias[n]  (+ epilogue)
// EPI: 0 = bias, 1 = bias + exact GELU, 2 = bias + residual res[m*N+n]
// BM=128, BN=64, BK=20, 128 threads, 8x8 microtile (16 ty x 8 tx).
// A: LDG->registers->transposed STS (double buffer);
// B: cp.async 16B direct to smem (no transpose needed, no staging regs).
// OOB B columns pre-zeroed once. Packed fma.rn.f32x2 compute.
#define BM 128
#define BN 64
#define BK 20
#define GTHREADS 128

template <int EPI>
__global__ void __launch_bounds__(GTHREADS, 4) sgemm(
    const float* __restrict__ A, const float* __restrict__ B,
    const float* __restrict__ bias, const float* __restrict__ res,
    float* __restrict__ C, int M, int N, int K, int ldc) {

    __shared__ __align__(16) float As[2][BK][BM];   // 20KB
    __shared__ __align__(16) float Bs[2][BK][BN];   // 10KB

    int tid = threadIdx.x;
    int tx = tid & 7;          // 8 column-groups (8 cols each)
    int ty = tid >> 3;         // 16 row-groups (8 rows each)
    int m0 = blockIdx.x * BM;
    int n0 = blockIdx.y * BN;

    // A tile: 128x20 floats = 640 float4, 128 threads -> 5 each (all full)
    int a_row[5], a_kq[5];
#pragma unroll
    for (int j = 0; j < 5; j++) {
        int idx = tid + GTHREADS * j;
        a_row[j] = idx / 5;
        a_kq[j]  = idx % 5;
    }
    // B tile: 20x64 floats = 320 float4 -> idx = tid, tid+128, tid+256(<64)
    int b_kk[3], b_nq[3];
#pragma unroll
    for (int j = 0; j < 3; j++) {
        int idx = tid + GTHREADS * j;
        b_kk[j] = idx / 16;
        b_nq[j] = idx % 16;
    }
    const bool b_v2 = (tid < 64);

    float4 ra[5];

#define LOAD_A(k0)                                                            \
    {                                                                          \
        _Pragma("unroll")                                                      \
        for (int j = 0; j < 5; j++)                                            \
            ra[j] = *reinterpret_cast<const float4*>(                          \
                &A[(size_t)(m0 + a_row[j]) * K + (k0) + a_kq[j] * 4]);         \
    }

#define STORE_A(buf)                                                          \
    {                                                                          \
        _Pragma("unroll")                                                      \
        for (int j = 0; j < 5; j++) {                                          \
            As[buf][a_kq[j] * 4 + 0][a_row[j]] = ra[j].x;                      \
            As[buf][a_kq[j] * 4 + 1][a_row[j]] = ra[j].y;                      \
            As[buf][a_kq[j] * 4 + 2][a_row[j]] = ra[j].z;                      \
            As[buf][a_kq[j] * 4 + 3][a_row[j]] = ra[j].w;                      \
        }                                                                      \
    }

#define ISSUE_B(k0, buf)                                                      \
    {                                                                          \
        _Pragma("unroll")                                                      \
        for (int j = 0; j < 3; j++) {                                          \
            if (j < 2 || b_v2) {                                               \
                int n = n0 + b_nq[j] * 4;                                      \
                if (n < N)                                                     \
                    cp_async16(&Bs[buf][b_kk[j]][b_nq[j] * 4],                 \
                               &B[(size_t)((k0) + b_kk[j]) * N + n]);          \
            }                                                                  \
        }                                                                      \
        cp_async_commit();                                                     \
    }

    // pre-zero Bs (covers OOB columns that cp.async never writes)
#pragma unroll
    for (int j = 0; j < 5; j++) {
        int idx = tid + GTHREADS * j;   // 640 float4 covers 2*20*64 floats
        reinterpret_cast<float4*>(&Bs[0][0][0])[idx] =
            make_float4(0.f, 0.f, 0.f, 0.f);
    }
    __syncthreads();

    ull acc2[4][8];
#pragma unroll
    for (int i = 0; i < 4; i++)
#pragma unroll
        for (int j = 0; j < 8; j++) acc2[i][j] = 0ull;

    int nstage = K / BK;

    // prologue: stage 0 into buffer 0
    ISSUE_B(0, 0)
    LOAD_A(0)
    STORE_A(0)
    cp_async_wait0();
    __syncthreads();

    for (int kt = 0; kt < nstage; kt++) {
        int buf = kt & 1;
        if (kt + 1 < nstage) {
            ISSUE_B((kt + 1) * BK, buf ^ 1)   // async into idle buffer
            LOAD_A((kt + 1) * BK)             // LDG overlaps compute
        }

#pragma unroll
        for (int kk = 0; kk < BK; kk++) {
            const ulonglong2* ar =
                reinterpret_cast<const ulonglong2*>(&As[buf][kk][ty * 8]);
            ulonglong2 a01 = ar[0], a23 = ar[1];
            ull ap[4] = {a01.x, a01.y, a23.x, a23.y};
            const float4* br =
                reinterpret_cast<const float4*>(&Bs[buf][kk][tx * 8]);
            float4 b0 = br[0], b1 = br[1];
            float bv[8] = {b0.x, b0.y, b0.z, b0.w, b1.x, b1.y, b1.z, b1.w};
#pragma unroll
            for (int j = 0; j < 8; j++) {
                ull bd = dup2(bv[j]);
#pragma unroll
                for (int i = 0; i < 4; i++) ffma2(acc2[i][j], ap[i], bd);
            }
        }

        if (kt + 1 < nstage) STORE_A(buf ^ 1)   // safe: buf^1 idle since sync
        cp_async_wait0();
        __syncthreads();
    }

    // -------- vectorized epilogue (N % 4 == 0; strides 16B-aligned) ------
    int n4 = n0 + tx * 8;
#pragma unroll
    for (int half = 0; half < 2; half++) {
        int nh = n4 + 4 * half;
        if (nh < N) {
            float4 bv = *reinterpret_cast<const float4*>(&bias[nh]);
            float bb[4] = {bv.x, bv.y, bv.z, bv.w};
#pragma unroll
            for (int i2 = 0; i2 < 4; i2++) {
                float va[2][4];
#pragma unroll
                for (int j = 0; j < 4; j++)
                    unpack2(acc2[i2][4 * half + j], va[0][j], va[1][j]);
#pragma unroll
                for (int r = 0; r < 2; r++) {
                    int ma = m0 + ty * 8 + 2 * i2 + r;
#pragma unroll
                    for (int j = 0; j < 4; j++) {
                        float v = va[r][j] + bb[j];
                        if (EPI == 1)
                            v = 0.5f * v *
                                (1.0f + erff(v * 0.70710678118654752f));
                        va[r][j] = v;
                    }
                    if (EPI == 2) {
                        float4 rv = *reinterpret_cast<const float4*>(
                            &res[(size_t)ma * N + nh]);
                        va[r][0] += rv.x; va[r][1] += rv.y;
                        va[r][2] += rv.z; va[r][3] += rv.w;
                    }
                    *reinterpret_cast<float4*>(&C[(size_t)ma * ldc + nh]) =
                        make_float4(va[r][0], va[r][1], va[r][2], va[r][3]);
                }
            }
        }
    }
#undef LOAD_A
#undef STORE_A
#undef ISSUE_B
}

// ---------------------------- Attention -----------------------------
// One block per (window, head): 256 threads, one query each.
// KV processed in TWO halves of 288 keys so smem = 73.7KB -> 2 CTAs/SM.
// Online softmax carries across halves. 2-stage software pipeline over keys:
// the QK dot for key k+1 issues while key k's reduce->exp->PV chain drains.
// Output written as float2 (base pix*180+h*30 always even -> 8B aligned).
__global__ void __launch_bounds__(256, 2) attn_kernel(
    const float* __restrict__ qkv, const float* __restrict__ biasT,
    float* __restrict__ out) {

    extern __shared__ float smem[];
    float* ksm = smem;                     // NKVH * HDP floats
    float* vsm = smem + NKVH * HDP;        // NKVH * HDP floats

    int win = blockIdx.x;
    int h   = blockIdx.y;
    int wy  = win >> 4, wx = win & 15;
    int tid = threadIdx.x;

    int qy = tid >> 4, qx = tid & 15;
    size_t pix = (size_t)(wy * 16 + qy) * IMGW + (wx * 16 + qx);
    const float scale = rsqrtf((float)HD);
    ull q2[16];
    {
        float qtmp[HDP];
        const float* qp = qkv + pix * QKVW + h * HD;
#pragma unroll
        for (int d = 0; d < HD; d++) qtmp[d] = qp[d] * scale;
        qtmp[30] = 0.f; qtmp[31] = 0.f;
#pragma unroll
        for (int i = 0; i < 16; i++) q2[i] = pack2(qtmp[2 * i], qtmp[2 * i + 1]);
    }

    const float* bT = biasT + (size_t)h * NKV * NQ + tid;
    float m = -1e30f, l = 0.f;
    ull acc2[16];
#pragma unroll
    for (int i = 0; i < 16; i++) acc2[i] = 0ull;

    // 2-deep rolling bias prefetch (global key index)
    float bcur = bT[0];
    float bnx1 = bT[NQ];

    for (int half = 0; half < 2; half++) {
        int kbase = half * NKVH;
        __syncthreads();   // previous half's compute done before restage

        // stage 288 keys as float2: 16 slots per key (slot 15 = pad 30,31)
#pragma unroll 6
        for (int idx = tid; idx < NKVH * 16; idx += 256) {
            int loc = idx >> 4;            // local key 0..287
            int dd  = idx & 15;            // float2 slot
            int pos = kbase + loc;
            int ky = pos / 24, kx = pos - ky * 24;
            int r = wy * 16 - 4 + ky;
            int c = wx * 16 - 4 + kx;
            float2 kk = make_float2(0.f, 0.f), vv = make_float2(0.f, 0.f);
            if (dd < 15 && (unsigned)r < (unsigned)IMGW && (unsigned)c < (unsigned)IMGW) {
                const float* base = qkv + (size_t)(r * IMGW + c) * QKVW + h * HD + 2 * dd;
                kk = *reinterpret_cast<const float2*>(base + DIMC);       // K
                vv = *reinterpret_cast<const float2*>(base + 2 * DIMC);   // V
            }
            *reinterpret_cast<float2*>(ksm + loc * HDP + 2 * dd) = kk;
            *reinterpret_cast<float2*>(vsm + loc * HDP + 2 * dd) = vv;
        }
        __syncthreads();

        // pipeline prologue: dot for local key 0
        ull s01 = 0ull, s23 = 0ull, s45 = 0ull, s67 = 0ull;
        {
            const ulonglong2* kr = reinterpret_cast<const ulonglong2*>(ksm);
#pragma unroll
            for (int i = 0; i < 4; i++) {
                ulonglong2 ka = kr[2 * i];
                ulonglong2 kb = kr[2 * i + 1];
                ffma2(s01, q2[4 * i + 0], ka.x);
                ffma2(s23, q2[4 * i + 1], ka.y);
                ffma2(s45, q2[4 * i + 2], kb.x);
                ffma2(s67, q2[4 * i + 3], kb.y);
            }
        }

        for (int kl = 0; kl < NKVH; kl++) {
            int k = kbase + kl;
            float bnx2 = (k + 2 < NKV) ? bT[(size_t)(k + 2) * NQ] : 0.f;

            // reduce current dot (key kl)
            fadd2(s01, s23);
            fadd2(s45, s67);
            fadd2(s01, s45);
            float f0, f1;
            unpack2(s01, f0, f1);
            float s = f0 + f1 + bcur;
            bcur = bnx1; bnx1 = bnx2;

            // start next dot (key kl+1; dummy re-dot of kl on last iter)
            int kn = (kl + 1 < NKVH) ? kl + 1 : kl;
            const ulonglong2* krn =
                reinterpret_cast<const ulonglong2*>(ksm + kn * HDP);
            ull t01 = 0ull, t23 = 0ull, t45 = 0ull, t67 = 0ull;
#pragma unroll
            for (int i = 0; i < 4; i++) {
                ulonglong2 ka = krn[2 * i];
                ulonglong2 kb = krn[2 * i + 1];
                ffma2(t01, q2[4 * i + 0], ka.x);
                ffma2(t23, q2[4 * i + 1], ka.y);
                ffma2(t45, q2[4 * i + 2], kb.x);
                ffma2(t67, q2[4 * i + 3], kb.y);
            }

            // softmax update for key kl (exp latency overlapped by next dot)
            if (s > m) {
                float cf = __expf(m - s);
                l *= cf;
                ull cf2 = dup2(cf);
#pragma unroll
                for (int i = 0; i < 16; i++) fmul2(acc2[i], cf2);
                m = s;
            }
            float e = __expf(s - m);
            l += e;
            ull e2 = dup2(e);
            const ulonglong2* vr =
                reinterpret_cast<const ulonglong2*>(vsm + kl * HDP);
#pragma unroll
            for (int i = 0; i < 8; i++) {
                ulonglong2 vv = vr[i];
                ffma2(acc2[2 * i], e2, vv.x);
                ffma2(acc2[2 * i + 1], e2, vv.y);
            }

            s01 = t01; s23 = t23; s45 = t45; s67 = t67;
        }
    }

    float inv = 1.f / l;
    float* op = out + pix * DIMC + h * HD;   // even offset -> 8B aligned
#pragma unroll
    for (int i = 0; i < 15; i++) {           // 30 = 15 float2
        float a, b;
        unpack2(acc2[i], a, b);
        *reinterpret_cast<float2*>(op + 2 * i) = make_float2(a * inv, b * inv);
    }

}

// ---------------------------- launch --------------------------------
extern "C" void kernel_launch(void* const* d_in, const int* in_sizes, int n_in,
                              void* d_out, int out_size) {
    // input order: x, rpi, [h, w,] norm1_g, norm1_b, q_w, q_b, kv_w, kv_b,
    //              rpb_table, proj_w, proj_b, norm2_g, norm2_b,
    //              mlp_w1, mlp_b1, mlp_w2, mlp_b2
    int s = (n_in >= 19) ? 2 : 0;   // skip h,w scalars if present
    const float* x    = (const float*)d_in[0];
    const int*   rpi  = (const int*)d_in[1];
    const float* n1g  = (const float*)d_in[2 + s];
    const float* n1b  = (const float*)d_in[3 + s];
    const float* qw   = (const float*)d_in[4 + s];
    const float* qb   = (const float*)d_in[5 + s];
    const float* kvw  = (const float*)d_in[6 + s];
    const float* kvb  = (const float*)d_in[7 + s];
    const float* tab  = (const float*)d_in[8 + s];
    const float* pw   = (const float*)d_in[9 + s];
    const float* pb   = (const float*)d_in[10 + s];
    const float* n2g  = (const float*)d_in[11 + s];
    const float* n2b  = (const float*)d_in[12 + s];
    const float* w1   = (const float*)d_in[13 + s];
    const float* b1   = (const float*)d_in[14 + s];
    const float* w2   = (const float*)d_in[15 + s];
    const float* b2   = (const float*)d_in[16 + s];
    float* outp = (float*)d_out;

    float *xn, *qkv, *biasT, *attn, *xo, *xn2, *hid;
    cudaGetSymbolAddress((void**)&xn,    g_xn);
    cudaGetSymbolAddress((void**)&qkv,   g_qkv);
    cudaGetSymbolAddress((void**)&biasT, g_biasT);
    cudaGetSymbolAddress((void**)&attn,  g_attn);
    cudaGetSymbolAddress((void**)&xo,    g_xo);
    cudaGetSymbolAddress((void**)&xn2,   g_xn2);
    cudaGetSymbolAddress((void**)&hid,   g_hid);

    dim3 lnb(32, 8);

    // 1) LN1
    ln_kernel<<<L_TOK / 8, lnb>>>(x, n1g, n1b, xn);
    // 2) bias table (independent of LN)
    bias_kernel<<<dim3(NKV, NHEADS), NQ>>>(rpi, tab, biasT);
    // 3) Q and KV projections into one 540-wide buffer
    sgemm<0><<<dim3(L_TOK / BM, (DIMC + BN - 1) / BN), GTHREADS>>>(
        xn, qw, qb, nullptr, qkv, L_TOK, DIMC, DIMC, QKVW);
    sgemm<0><<<dim3(L_TOK / BM, (2 * DIMC + BN - 1) / BN), GTHREADS>>>(
        xn, kvw, kvb, nullptr, qkv + DIMC, L_TOK, 2 * DIMC, DIMC, QKVW);
    // 4) fused windowed attention (half-window smem: 2*288*32*4 = 73728 B)
    size_t attn_smem = (size_t)NKVH * HDP * 2 * sizeof(float);
    cudaFuncSetAttribute(attn_kernel,
                         cudaFuncAttributeMaxDynamicSharedMemorySize,
                         (int)attn_smem);
    attn_kernel<<<dim3(NWIN, NHEADS), 256, attn_smem>>>(qkv, biasT, attn);
    // 5) output projection + residual(x)
    sgemm<2><<<dim3(L_TOK / BM, (DIMC + BN - 1) / BN), GTHREADS>>>(
        attn, pw, pb, x, xo, L_TOK, DIMC, DIMC, DIMC);
    // 6) LN2
    ln_kernel<<<L_TOK / 8, lnb>>>(xo, n2g, n2b, xn2);
    // 7) MLP up + GELU
    sgemm<1><<<dim3(L_TOK / BM, (MLPH + BN - 1) / BN), GTHREADS>>>(
        xn2, w1, b1, nullptr, hid, L_TOK, MLPH, DIMC, MLPH);
    // 8) MLP down + residual(xo) -> d_out
    sgemm<2><<<dim3(L_TOK / BM, (DIMC + BN - 1) / BN), GTHREADS>>>(
        hid, w2, b2, xo, outp, L_TOK, DIMC, MLPH, DIMC);
}